// round 1
// baseline (speedup 1.0000x reference)
#include <cuda_runtime.h>

#define BB   512
#define CC   512
#define EE   128
#define HWW  240
#define GATES 1536   // 3*C
#define KX    640    // C+E

// Scratch (no allocation allowed in kernel_launch)
__device__ float g_x [BB * KX];     // [B, C+E]  concat(context, embeddings)
__device__ float g_gi[BB * GATES];  // x @ w_ih^T + b_ih
__device__ float g_gh[BB * GATES];  // h @ w_hh^T + b_hh

__device__ __forceinline__ float tanh_fast(float x) {
    float y; asm("tanh.approx.f32 %0, %1;" : "=f"(y) : "f"(x)); return y;
}
__device__ __forceinline__ float sigmoid_fast(float x) {
    return 0.5f * tanh_fast(0.5f * x) + 0.5f;
}

// ---------------------------------------------------------------------------
// Kernel 1: fused additive-attention score + softmax + context, one block per b.
// ---------------------------------------------------------------------------
__global__ __launch_bounds__(256) void attn_kernel(
    const float* __restrict__ ph,    // [B, C]
    const float* __restrict__ cf,    // [B, C, HW]
    const float* __restrict__ cfo,   // [B, C, HW]
    const float* __restrict__ emb,   // [B, E]
    const float* __restrict__ sw,    // [C]
    float* __restrict__ alphaT)      // [HW, B]
{
    const int b   = blockIdx.x;
    const int tid = threadIdx.x;

    __shared__ float s_ph[CC];
    __shared__ float s_sw[CC];
    __shared__ float s_alpha[HWW];
    __shared__ float s_red[8];
    __shared__ float s_red2[8];

    for (int i = tid; i < CC; i += 256) {
        s_ph[i] = ph[(size_t)b * CC + i];
        s_sw[i] = sw[i];
    }
    __syncthreads();

    // Phase A: emition[h] = sum_c tanh(cf[b,c,h] + ph[b,c]) * sw[c]
    float acc = 0.f;
    if (tid < HWW) {
        const float* p = cf + (size_t)b * CC * HWW + tid;
        #pragma unroll 4
        for (int c = 0; c < CC; ++c) {
            acc += tanh_fast(p[(size_t)c * HWW] + s_ph[c]) * s_sw[c];
        }
    }

    // Phase B: softmax over 240 positions
    float v = (tid < HWW) ? acc : -3.0e38f;
    #pragma unroll
    for (int o = 16; o; o >>= 1) v = fmaxf(v, __shfl_xor_sync(0xffffffffu, v, o));
    if ((tid & 31) == 0) s_red[tid >> 5] = v;
    __syncthreads();
    float m = s_red[0];
    #pragma unroll
    for (int i = 1; i < 8; ++i) m = fmaxf(m, s_red[i]);

    float e = (tid < HWW) ? __expf(acc - m) : 0.f;
    float sv = e;
    #pragma unroll
    for (int o = 16; o; o >>= 1) sv += __shfl_xor_sync(0xffffffffu, sv, o);
    if ((tid & 31) == 0) s_red2[tid >> 5] = sv;
    __syncthreads();
    float tot = 0.f;
    #pragma unroll
    for (int i = 0; i < 8; ++i) tot += s_red2[i];

    const float alpha = e / tot;
    if (tid < HWW) {
        s_alpha[tid] = alpha;
        alphaT[(size_t)tid * BB + b] = alpha;   // alpha.T output [HW, B]
    }
    __syncthreads();

    // Phase C: context[c] = sum_h cfo[b,c,h] * alpha[h]  (warp per channel row)
    const int warp = tid >> 5, lane = tid & 31;
    for (int c = warp; c < CC; c += 8) {
        const float* p = cfo + ((size_t)b * CC + c) * HWW;
        float s0 = 0.f;
        #pragma unroll
        for (int i = 0; i < 7; ++i) {
            int h = lane + i * 32;
            s0 += p[h] * s_alpha[h];
        }
        if (lane < 16) {                         // 240 = 7*32 + 16
            int h = lane + 224;
            s0 += p[h] * s_alpha[h];
        }
        #pragma unroll
        for (int o = 16; o; o >>= 1) s0 += __shfl_xor_sync(0xffffffffu, s0, o);
        if (lane == 0) g_x[(size_t)b * KX + c] = s0;
    }
    // concat embeddings
    if (tid < EE) g_x[(size_t)b * KX + CC + tid] = emb[(size_t)b * EE + tid];
}

// ---------------------------------------------------------------------------
// Kernel 2: gate GEMMs.  z=0: gi = g_x @ w_ih^T + b_ih  (K=640)
//                        z=1: gh = h   @ w_hh^T + b_hh  (K=512)
// Tiles: 64(M) x 64(N) x 16(K), 128 threads, 8x4 microtile per thread.
// ---------------------------------------------------------------------------
__global__ __launch_bounds__(128) void gemm_gates(
    const float* __restrict__ hprev,
    const float* __restrict__ w_ih, const float* __restrict__ w_hh,
    const float* __restrict__ b_ih, const float* __restrict__ b_hh)
{
    const int z = blockIdx.z;
    const float* A    = z ? hprev : g_x;
    const float* Wm   = z ? w_hh  : w_ih;
    const float* bias = z ? b_hh  : b_ih;
    float*       out  = z ? g_gh  : g_gi;
    const int    K    = z ? CC    : KX;

    __shared__ __align__(16) float As[16][68];
    __shared__ __align__(16) float Bs[16][68];

    const int tid  = threadIdx.x;
    const int row  = tid >> 1;          // 0..63
    const int kseg = (tid & 1) * 8;     // 0 or 8
    const int m0   = blockIdx.y * 64;
    const int n0   = blockIdx.x * 64;
    const int ty   = tid >> 4;          // 0..7  -> 8 M-rows each
    const int tx   = tid & 15;          // 0..15 -> 4 N-cols each

    float acc[8][4];
    #pragma unroll
    for (int i = 0; i < 8; ++i)
        #pragma unroll
        for (int j = 0; j < 4; ++j) acc[i][j] = 0.f;

    for (int kk = 0; kk < K; kk += 16) {
        const float4* pa = reinterpret_cast<const float4*>(
            A + (size_t)(m0 + row) * K + kk + kseg);
        float4 a0 = pa[0], a1 = pa[1];
        const float4* pb = reinterpret_cast<const float4*>(
            Wm + (size_t)(n0 + row) * K + kk + kseg);
        float4 b0 = pb[0], b1 = pb[1];

        __syncthreads();   // previous compute done before overwrite
        As[kseg + 0][row] = a0.x; As[kseg + 1][row] = a0.y;
        As[kseg + 2][row] = a0.z; As[kseg + 3][row] = a0.w;
        As[kseg + 4][row] = a1.x; As[kseg + 5][row] = a1.y;
        As[kseg + 6][row] = a1.z; As[kseg + 7][row] = a1.w;
        Bs[kseg + 0][row] = b0.x; Bs[kseg + 1][row] = b0.y;
        Bs[kseg + 2][row] = b0.z; Bs[kseg + 3][row] = b0.w;
        Bs[kseg + 4][row] = b1.x; Bs[kseg + 5][row] = b1.y;
        Bs[kseg + 6][row] = b1.z; Bs[kseg + 7][row] = b1.w;
        __syncthreads();

        #pragma unroll
        for (int k = 0; k < 16; ++k) {
            float4 af0 = *reinterpret_cast<const float4*>(&As[k][ty * 8]);
            float4 af1 = *reinterpret_cast<const float4*>(&As[k][ty * 8 + 4]);
            float4 bf  = *reinterpret_cast<const float4*>(&Bs[k][tx * 4]);
            float a[8] = {af0.x, af0.y, af0.z, af0.w, af1.x, af1.y, af1.z, af1.w};
            float bb[4] = {bf.x, bf.y, bf.z, bf.w};
            #pragma unroll
            for (int i = 0; i < 8; ++i)
                #pragma unroll
                for (int j = 0; j < 4; ++j)
                    acc[i][j] += a[i] * bb[j];
        }
    }

    float4 bv = *reinterpret_cast<const float4*>(bias + n0 + tx * 4);
    #pragma unroll
    for (int i = 0; i < 8; ++i) {
        float4 o;
        o.x = acc[i][0] + bv.x;
        o.y = acc[i][1] + bv.y;
        o.z = acc[i][2] + bv.z;
        o.w = acc[i][3] + bv.w;
        *reinterpret_cast<float4*>(
            out + (size_t)(m0 + ty * 8 + i) * GATES + n0 + tx * 4) = o;
    }
}

// ---------------------------------------------------------------------------
// Kernel 3: GRU combine (PyTorch GRUCell semantics)
// ---------------------------------------------------------------------------
__global__ __launch_bounds__(256) void gru_kernel(
    const float* __restrict__ h, float* __restrict__ out)
{
    const int idx = blockIdx.x * 256 + threadIdx.x;   // grid covers B*C exactly
    const int b = idx >> 9;
    const int c = idx & 511;
    const float* pi = g_gi + (size_t)b * GATES;
    const float* pg = g_gh + (size_t)b * GATES;
    const float r  = sigmoid_fast(pi[c]          + pg[c]);
    const float zz = sigmoid_fast(pi[CC + c]     + pg[CC + c]);
    const float n  = tanh_fast  (pi[2 * CC + c] + r * pg[2 * CC + c]);
    const float hv = h[idx];
    out[idx] = (1.f - zz) * n + zz * hv;
}

// ---------------------------------------------------------------------------
extern "C" void kernel_launch(void* const* d_in, const int* in_sizes, int n_in,
                              void* d_out, int out_size) {
    const float* prev_hidden       = (const float*)d_in[0];
    const float* conv_feats        = (const float*)d_in[1];
    const float* conv_feats_origin = (const float*)d_in[2];
    const float* cur_embeddings    = (const float*)d_in[3];
    const float* score_w           = (const float*)d_in[4];
    const float* w_ih              = (const float*)d_in[5];
    const float* w_hh              = (const float*)d_in[6];
    const float* b_ih              = (const float*)d_in[7];
    const float* b_hh              = (const float*)d_in[8];

    float* out        = (float*)d_out;
    float* out_hidden = out;                      // [B, C]
    float* out_alphaT = out + (size_t)BB * CC;    // [HW, B]

    attn_kernel<<<BB, 256>>>(prev_hidden, conv_feats, conv_feats_origin,
                             cur_embeddings, score_w, out_alphaT);

    dim3 g(GATES / 64, BB / 64, 2);               // (24, 8, 2) = 384 CTAs
    gemm_gates<<<g, 128>>>(prev_hidden, w_ih, w_hh, b_ih, b_hh);

    gru_kernel<<<(BB * CC) / 256, 256>>>(prev_hidden, out_hidden);
}

// round 2
// speedup vs baseline: 1.2369x; 1.2369x over previous
#include <cuda_runtime.h>
#include <cuda_bf16.h>
#include <cstdint>

#define BB   512
#define CC   512
#define EE   128
#define HWW  240
#define GATES 1536   // 3*C
#define KX    640    // C+E

// -------- scratch (static device arrays; no allocation allowed) -----------
__device__ float g_gi[BB * GATES];
__device__ float g_gh[BB * GATES];

__device__ __nv_bfloat16 g_xhi [BB * KX];
__device__ __nv_bfloat16 g_xlo [BB * KX];
__device__ __nv_bfloat16 g_hhi [BB * CC];
__device__ __nv_bfloat16 g_hlo [BB * CC];
__device__ __nv_bfloat16 g_wihhi[GATES * KX];
__device__ __nv_bfloat16 g_wihlo[GATES * KX];
__device__ __nv_bfloat16 g_whhhi[GATES * CC];
__device__ __nv_bfloat16 g_whhlo[GATES * CC];

__device__ __forceinline__ float tanh_fast(float x) {
    float y; asm("tanh.approx.f32 %0, %1;" : "=f"(y) : "f"(x)); return y;
}
__device__ __forceinline__ float sigmoid_fast(float x) {
    return 0.5f * tanh_fast(0.5f * x) + 0.5f;
}
__device__ __forceinline__ void split_bf16(float v, __nv_bfloat16& hi, __nv_bfloat16& lo) {
    hi = __float2bfloat16(v);
    lo = __float2bfloat16(v - __bfloat162float(hi));
}

// ---------------------------------------------------------------------------
// split kernel: fp32 -> (bf16 hi, bf16 lo)
// ---------------------------------------------------------------------------
__global__ __launch_bounds__(256) void split_kernel(
    const float* __restrict__ src, __nv_bfloat16* __restrict__ hi,
    __nv_bfloat16* __restrict__ lo, int n)
{
    int i = blockIdx.x * 256 + threadIdx.x;
    if (i < n) {
        float v = src[i];
        __nv_bfloat16 h, l;
        split_bf16(v, h, l);
        hi[i] = h; lo[i] = l;
    }
}

// ---------------------------------------------------------------------------
// Kernel 1: fused attention score + softmax + context. One block per b,
// 512 threads. Phase A: 8 channel-groups x 60 threads, float4 over h.
// ---------------------------------------------------------------------------
__global__ __launch_bounds__(512) void attn_kernel(
    const float* __restrict__ ph,    // [B, C]
    const float* __restrict__ cf,    // [B, C, HW]
    const float* __restrict__ cfo,   // [B, C, HW]
    const float* __restrict__ emb,   // [B, E]
    const float* __restrict__ sw,    // [C]
    float* __restrict__ alphaT)      // [HW, B]
{
    const int b   = blockIdx.x;
    const int tid = threadIdx.x;

    __shared__ __align__(16) float s_ph[CC];
    __shared__ __align__(16) float s_sw[CC];
    __shared__ __align__(16) float s_part[8][HWW];
    __shared__ __align__(16) float s_alpha[HWW];
    __shared__ float s_red[16];
    __shared__ float s_red2[16];

    for (int i = tid; i < CC; i += 512) {
        s_ph[i] = ph[(size_t)b * CC + i];
        s_sw[i] = sw[i];
    }
    __syncthreads();

    // Phase A: group g covers channels [g*64, g*64+64), thread t covers h [4t,4t+4)
    const int g = tid >> 6;
    const int t = tid & 63;
    const bool valid = (t < 60);
    float4 acc4 = make_float4(0.f, 0.f, 0.f, 0.f);
    if (valid) {
        const float4* p4 = reinterpret_cast<const float4*>(
            cf + ((size_t)b * CC + g * 64) * HWW) + t;
        #pragma unroll 4
        for (int i = 0; i < 64; ++i) {
            float4 v = p4[(size_t)i * (HWW / 4)];
            float hp = s_ph[g * 64 + i];
            float w  = s_sw[g * 64 + i];
            acc4.x += tanh_fast(v.x + hp) * w;
            acc4.y += tanh_fast(v.y + hp) * w;
            acc4.z += tanh_fast(v.z + hp) * w;
            acc4.w += tanh_fast(v.w + hp) * w;
        }
        const int h = 4 * t;
        s_part[g][h + 0] = acc4.x;
        s_part[g][h + 1] = acc4.y;
        s_part[g][h + 2] = acc4.z;
        s_part[g][h + 3] = acc4.w;
    }
    __syncthreads();

    // reduce 8 partials, softmax over 240
    float eval = 0.f;
    if (tid < HWW) {
        #pragma unroll
        for (int gg = 0; gg < 8; ++gg) eval += s_part[gg][tid];
    }
    const int lane = tid & 31, wid = tid >> 5;

    float v = (tid < HWW) ? eval : -3.0e38f;
    #pragma unroll
    for (int o = 16; o; o >>= 1) v = fmaxf(v, __shfl_xor_sync(0xffffffffu, v, o));
    if (lane == 0) s_red[wid] = v;
    __syncthreads();
    float m = s_red[0];
    #pragma unroll
    for (int i = 1; i < 16; ++i) m = fmaxf(m, s_red[i]);

    float e = (tid < HWW) ? __expf(eval - m) : 0.f;
    float sv = e;
    #pragma unroll
    for (int o = 16; o; o >>= 1) sv += __shfl_xor_sync(0xffffffffu, sv, o);
    if (lane == 0) s_red2[wid] = sv;
    __syncthreads();
    float tot = 0.f;
    #pragma unroll
    for (int i = 0; i < 16; ++i) tot += s_red2[i];

    const float alpha = e / tot;
    if (tid < HWW) {
        s_alpha[tid] = alpha;
        alphaT[(size_t)tid * BB + b] = alpha;
    }
    // embeddings -> x tail (independent of s_alpha)
    if (tid < EE) {
        __nv_bfloat16 h, l;
        split_bf16(emb[(size_t)b * EE + tid], h, l);
        g_xhi[(size_t)b * KX + CC + tid] = h;
        g_xlo[(size_t)b * KX + CC + tid] = l;
    }
    __syncthreads();

    // Phase C: context[c] = sum_h cfo[b,c,h] * alpha[h]; warp per row, float4
    const float4* a4 = reinterpret_cast<const float4*>(s_alpha);
    for (int c = wid; c < CC; c += 16) {
        const float4* rp = reinterpret_cast<const float4*>(
            cfo + ((size_t)b * CC + c) * HWW);
        float4 vv = rp[lane];
        float4 aa = a4[lane];
        float s = vv.x * aa.x + vv.y * aa.y + vv.z * aa.z + vv.w * aa.w;
        if (lane < 28) {
            float4 v2 = rp[lane + 32];
            float4 a2 = a4[lane + 32];
            s += v2.x * a2.x + v2.y * a2.y + v2.z * a2.z + v2.w * a2.w;
        }
        #pragma unroll
        for (int o = 16; o; o >>= 1) s += __shfl_xor_sync(0xffffffffu, s, o);
        if (lane == 0) {
            __nv_bfloat16 h, l;
            split_bf16(s, h, l);
            g_xhi[(size_t)b * KX + c] = h;
            g_xlo[(size_t)b * KX + c] = l;
        }
    }
}

// ---------------------------------------------------------------------------
// Kernel 2: gate GEMMs on tensor cores (bf16 split, 3-MMA trick).
//  z=0: gi = x @ w_ih^T + b_ih  (K=640)   z=1: gh = h @ w_hh^T + b_hh (K=512)
// CTA 128 threads (4 warps, 2x2), tile 64(M) x 64(N), K-tile 32.
// ---------------------------------------------------------------------------
#define ASTR 40   // padded bf16 row stride in smem

__device__ __forceinline__ void mma16816(float* c, const uint32_t* a, const uint32_t* b) {
    asm volatile(
        "mma.sync.aligned.m16n8k16.row.col.f32.bf16.bf16.f32 "
        "{%0,%1,%2,%3}, {%4,%5,%6,%7}, {%8,%9}, {%0,%1,%2,%3};"
        : "+f"(c[0]), "+f"(c[1]), "+f"(c[2]), "+f"(c[3])
        : "r"(a[0]), "r"(a[1]), "r"(a[2]), "r"(a[3]),
          "r"(b[0]), "r"(b[1]));
}

__global__ __launch_bounds__(128) void gemm_gates(
    const float* __restrict__ b_ih, const float* __restrict__ b_hh)
{
    const int z = blockIdx.z;
    const __nv_bfloat16* Ahi = z ? g_hhi   : g_xhi;
    const __nv_bfloat16* Alo = z ? g_hlo   : g_xlo;
    const __nv_bfloat16* Bhi = z ? g_whhhi : g_wihhi;
    const __nv_bfloat16* Blo = z ? g_whhlo : g_wihlo;
    const float*         bias = z ? b_hh   : b_ih;
    float*               outp = z ? g_gh   : g_gi;
    const int            K    = z ? CC     : KX;

    __shared__ __align__(16) __nv_bfloat16 sAh[64 * ASTR];
    __shared__ __align__(16) __nv_bfloat16 sAl[64 * ASTR];
    __shared__ __align__(16) __nv_bfloat16 sBh[64 * ASTR];
    __shared__ __align__(16) __nv_bfloat16 sBl[64 * ASTR];

    const int tid  = threadIdx.x;
    const int lane = tid & 31;
    const int wrp  = tid >> 5;
    const int warp_m = wrp >> 1;           // 0..1
    const int warp_n = wrp & 1;            // 0..1
    const int gID = lane >> 2;             // 0..7
    const int tig = lane & 3;              // 0..3
    const int m0 = blockIdx.y * 64;
    const int n0 = blockIdx.x * 64;

    float acc[2][4][4];
    #pragma unroll
    for (int i = 0; i < 2; ++i)
        #pragma unroll
        for (int j = 0; j < 4; ++j)
            #pragma unroll
            for (int k = 0; k < 4; ++k) acc[i][j][k] = 0.f;

    const int T = K / 32;
    uint4 pa[2], pal[2], pb[2], pbl[2];

    // load K-tile 0 into regs
    {
        #pragma unroll
        for (int j = 0; j < 2; ++j) {
            int u = tid + 128 * j;
            int row = u >> 2, seg = u & 3;
            pa [j] = *reinterpret_cast<const uint4*>(Ahi + (size_t)(m0 + row) * K + seg * 8);
            pal[j] = *reinterpret_cast<const uint4*>(Alo + (size_t)(m0 + row) * K + seg * 8);
            pb [j] = *reinterpret_cast<const uint4*>(Bhi + (size_t)(n0 + row) * K + seg * 8);
            pbl[j] = *reinterpret_cast<const uint4*>(Blo + (size_t)(n0 + row) * K + seg * 8);
        }
    }

    for (int tIdx = 0; tIdx < T; ++tIdx) {
        __syncthreads();
        #pragma unroll
        for (int j = 0; j < 2; ++j) {
            int u = tid + 128 * j;
            int row = u >> 2, seg = u & 3;
            *reinterpret_cast<uint4*>(&sAh[row * ASTR + seg * 8]) = pa[j];
            *reinterpret_cast<uint4*>(&sAl[row * ASTR + seg * 8]) = pal[j];
            *reinterpret_cast<uint4*>(&sBh[row * ASTR + seg * 8]) = pb[j];
            *reinterpret_cast<uint4*>(&sBl[row * ASTR + seg * 8]) = pbl[j];
        }
        __syncthreads();

        if (tIdx + 1 < T) {
            const int kk = (tIdx + 1) * 32;
            #pragma unroll
            for (int j = 0; j < 2; ++j) {
                int u = tid + 128 * j;
                int row = u >> 2, seg = u & 3;
                pa [j] = *reinterpret_cast<const uint4*>(Ahi + (size_t)(m0 + row) * K + kk + seg * 8);
                pal[j] = *reinterpret_cast<const uint4*>(Alo + (size_t)(m0 + row) * K + kk + seg * 8);
                pb [j] = *reinterpret_cast<const uint4*>(Bhi + (size_t)(n0 + row) * K + kk + seg * 8);
                pbl[j] = *reinterpret_cast<const uint4*>(Blo + (size_t)(n0 + row) * K + kk + seg * 8);
            }
        }

        #pragma unroll
        for (int k8 = 0; k8 < 2; ++k8) {
            const int kb = k8 * 16 + tig * 2;
            uint32_t ah[2][4], al[2][4];
            #pragma unroll
            for (int m2 = 0; m2 < 2; ++m2) {
                int r0 = warp_m * 32 + m2 * 16 + gID;
                ah[m2][0] = *reinterpret_cast<const uint32_t*>(&sAh[ r0      * ASTR + kb    ]);
                ah[m2][1] = *reinterpret_cast<const uint32_t*>(&sAh[(r0 + 8) * ASTR + kb    ]);
                ah[m2][2] = *reinterpret_cast<const uint32_t*>(&sAh[ r0      * ASTR + kb + 8]);
                ah[m2][3] = *reinterpret_cast<const uint32_t*>(&sAh[(r0 + 8) * ASTR + kb + 8]);
                al[m2][0] = *reinterpret_cast<const uint32_t*>(&sAl[ r0      * ASTR + kb    ]);
                al[m2][1] = *reinterpret_cast<const uint32_t*>(&sAl[(r0 + 8) * ASTR + kb    ]);
                al[m2][2] = *reinterpret_cast<const uint32_t*>(&sAl[ r0      * ASTR + kb + 8]);
                al[m2][3] = *reinterpret_cast<const uint32_t*>(&sAl[(r0 + 8) * ASTR + kb + 8]);
            }
            uint32_t bh[4][2], bl[4][2];
            #pragma unroll
            for (int n4 = 0; n4 < 4; ++n4) {
                int nn = warp_n * 32 + n4 * 8 + gID;
                bh[n4][0] = *reinterpret_cast<const uint32_t*>(&sBh[nn * ASTR + kb    ]);
                bh[n4][1] = *reinterpret_cast<const uint32_t*>(&sBh[nn * ASTR + kb + 8]);
                bl[n4][0] = *reinterpret_cast<const uint32_t*>(&sBl[nn * ASTR + kb    ]);
                bl[n4][1] = *reinterpret_cast<const uint32_t*>(&sBl[nn * ASTR + kb + 8]);
            }
            #pragma unroll
            for (int m2 = 0; m2 < 2; ++m2)
                #pragma unroll
                for (int n4 = 0; n4 < 4; ++n4) {
                    mma16816(acc[m2][n4], ah[m2], bh[n4]);
                    mma16816(acc[m2][n4], ah[m2], bl[n4]);
                    mma16816(acc[m2][n4], al[m2], bh[n4]);
                }
        }
    }

    // epilogue: + bias, write fp32
    #pragma unroll
    for (int m2 = 0; m2 < 2; ++m2) {
        #pragma unroll
        for (int n4 = 0; n4 < 4; ++n4) {
            int r = m0 + warp_m * 32 + m2 * 16 + gID;
            int cb = n0 + warp_n * 32 + n4 * 8 + tig * 2;
            float2 bv = *reinterpret_cast<const float2*>(bias + cb);
            float2 o0, o1;
            o0.x = acc[m2][n4][0] + bv.x;
            o0.y = acc[m2][n4][1] + bv.y;
            o1.x = acc[m2][n4][2] + bv.x;
            o1.y = acc[m2][n4][3] + bv.y;
            *reinterpret_cast<float2*>(outp + (size_t)r * GATES + cb) = o0;
            *reinterpret_cast<float2*>(outp + (size_t)(r + 8) * GATES + cb) = o1;
        }
    }
}

// ---------------------------------------------------------------------------
// Kernel 3: GRU combine (PyTorch GRUCell semantics)
// ---------------------------------------------------------------------------
__global__ __launch_bounds__(256) void gru_kernel(
    const float* __restrict__ h, float* __restrict__ out)
{
    const int idx = blockIdx.x * 256 + threadIdx.x;
    const int b = idx >> 9;
    const int c = idx & 511;
    const float* pi = g_gi + (size_t)b * GATES;
    const float* pg = g_gh + (size_t)b * GATES;
    const float r  = sigmoid_fast(pi[c]          + pg[c]);
    const float zz = sigmoid_fast(pi[CC + c]     + pg[CC + c]);
    const float n  = tanh_fast  (pi[2 * CC + c] + r * pg[2 * CC + c]);
    const float hv = h[idx];
    out[idx] = (1.f - zz) * n + zz * hv;
}

// ---------------------------------------------------------------------------
extern "C" void kernel_launch(void* const* d_in, const int* in_sizes, int n_in,
                              void* d_out, int out_size) {
    const float* prev_hidden       = (const float*)d_in[0];
    const float* conv_feats        = (const float*)d_in[1];
    const float* conv_feats_origin = (const float*)d_in[2];
    const float* cur_embeddings    = (const float*)d_in[3];
    const float* score_w           = (const float*)d_in[4];
    const float* w_ih              = (const float*)d_in[5];
    const float* w_hh              = (const float*)d_in[6];
    const float* b_ih              = (const float*)d_in[7];
    const float* b_hh              = (const float*)d_in[8];

    float* out        = (float*)d_out;
    float* out_hidden = out;                      // [B, C]
    float* out_alphaT = out + (size_t)BB * CC;    // [HW, B]

    // bf16 splits of weights and h (independent of attention)
    __nv_bfloat16 *wihhi, *wihlo, *whhhi, *whhlo, *hhi, *hlo;
    cudaGetSymbolAddress((void**)&wihhi, g_wihhi);
    cudaGetSymbolAddress((void**)&wihlo, g_wihlo);
    cudaGetSymbolAddress((void**)&whhhi, g_whhhi);
    cudaGetSymbolAddress((void**)&whhlo, g_whhlo);
    cudaGetSymbolAddress((void**)&hhi,   g_hhi);
    cudaGetSymbolAddress((void**)&hlo,   g_hlo);

    split_kernel<<<(GATES * KX + 255) / 256, 256>>>(w_ih, wihhi, wihlo, GATES * KX);
    split_kernel<<<(GATES * CC + 255) / 256, 256>>>(w_hh, whhhi, whhlo, GATES * CC);
    split_kernel<<<(BB * CC + 255) / 256, 256>>>(prev_hidden, hhi, hlo, BB * CC);

    attn_kernel<<<BB, 512>>>(prev_hidden, conv_feats, conv_feats_origin,
                             cur_embeddings, score_w, out_alphaT);

    dim3 g(GATES / 64, BB / 64, 2);               // (24, 8, 2) = 384 CTAs
    gemm_gates<<<g, 128>>>(b_ih, b_hh);

    gru_kernel<<<(BB * CC) / 256, 256>>>(prev_hidden, out_hidden);
}

// round 3
// speedup vs baseline: 1.6303x; 1.3180x over previous
#include <cuda_runtime.h>
#include <cuda_bf16.h>
#include <cstdint>

#define BB   512
#define CC   512
#define EE   128
#define HWW  240
#define GATES 1536   // 3*C
#define KX    640    // C+E

// -------- scratch (static device arrays; no allocation allowed) -----------
__device__ float g_gi[BB * GATES];
__device__ float g_gh[BB * GATES];
__device__ float g_alpha[BB * HWW];

__device__ __nv_bfloat16 g_xhi [BB * KX];
__device__ __nv_bfloat16 g_xlo [BB * KX];
__device__ __nv_bfloat16 g_hhi [BB * CC];
__device__ __nv_bfloat16 g_hlo [BB * CC];
__device__ __nv_bfloat16 g_wihhi[GATES * KX];
__device__ __nv_bfloat16 g_wihlo[GATES * KX];
__device__ __nv_bfloat16 g_whhhi[GATES * CC];
__device__ __nv_bfloat16 g_whhlo[GATES * CC];

__device__ __forceinline__ float tanh_fast(float x) {
    float y; asm("tanh.approx.f32 %0, %1;" : "=f"(y) : "f"(x)); return y;
}
__device__ __forceinline__ float sigmoid_fast(float x) {
    return 0.5f * tanh_fast(0.5f * x) + 0.5f;
}
__device__ __forceinline__ void split_bf16(float v, __nv_bfloat16& hi, __nv_bfloat16& lo) {
    hi = __float2bfloat16(v);
    lo = __float2bfloat16(v - __bfloat162float(hi));
}

// ---------------------------------------------------------------------------
// split3: fp32 -> (bf16 hi, bf16 lo) for w_ih, w_hh, prev_hidden, float4-wide.
// ---------------------------------------------------------------------------
#define N1 (GATES * KX)   // 983040
#define N2 (GATES * CC)   // 786432
#define N3 (BB * CC)      // 262144

__global__ __launch_bounds__(256) void split3_kernel(
    const float* __restrict__ w_ih, const float* __restrict__ w_hh,
    const float* __restrict__ h)
{
    int i = blockIdx.x * 256 + threadIdx.x;   // float4 index, grid covers exactly
    const float* src; __nv_bfloat16 *hi, *lo; int off;
    if (i < N1 / 4)            { src = w_ih; hi = g_wihhi; lo = g_wihlo; off = i; }
    else if (i < (N1 + N2) / 4){ src = w_hh; hi = g_whhhi; lo = g_whhlo; off = i - N1 / 4; }
    else                       { src = h;    hi = g_hhi;   lo = g_hlo;   off = i - (N1 + N2) / 4; }

    float4 v = reinterpret_cast<const float4*>(src)[off];
    __nv_bfloat16 h0, l0, h1, l1, h2, l2, h3, l3;
    split_bf16(v.x, h0, l0); split_bf16(v.y, h1, l1);
    split_bf16(v.z, h2, l2); split_bf16(v.w, h3, l3);
    __nv_bfloat162 ph0 = {h0, h1}, ph1 = {h2, h3};
    __nv_bfloat162 pl0 = {l0, l1}, pl1 = {l2, l3};
    uint2 uh = {*(uint32_t*)&ph0, *(uint32_t*)&ph1};
    uint2 ul = {*(uint32_t*)&pl0, *(uint32_t*)&pl1};
    reinterpret_cast<uint2*>(hi)[off] = uh;
    reinterpret_cast<uint2*>(lo)[off] = ul;
}

// ---------------------------------------------------------------------------
// Kernel 1: score + softmax. One block per b, 512 threads.
// 16 groups x 32 channels; thread t (<30) covers h [8t, 8t+8) via 2x float4.
// ---------------------------------------------------------------------------
__global__ __launch_bounds__(512) void score_kernel(
    const float* __restrict__ ph,    // [B, C]
    const float* __restrict__ cf,    // [B, C, HW]
    const float* __restrict__ emb,   // [B, E]
    const float* __restrict__ sw,    // [C]
    float* __restrict__ alphaT)      // [HW, B]
{
    const int b   = blockIdx.x;
    const int tid = threadIdx.x;

    __shared__ __align__(16) float s_ph[CC];
    __shared__ __align__(16) float s_sw[CC];
    __shared__ __align__(16) float s_part[16][HWW];
    __shared__ float s_red[16];
    __shared__ float s_red2[16];

    for (int i = tid; i < CC; i += 512) {
        s_ph[i] = ph[(size_t)b * CC + i];
        s_sw[i] = sw[i];
    }
    __syncthreads();

    const int g = tid >> 5;   // 0..15
    const int t = tid & 31;   // 0..31, only t<30 active
    if (t < 30) {
        const float4* p4 = reinterpret_cast<const float4*>(
            cf + ((size_t)b * CC + g * 32) * HWW) + 2 * t;
        float4 a0 = make_float4(0.f, 0.f, 0.f, 0.f);
        float4 a1 = make_float4(0.f, 0.f, 0.f, 0.f);
        #pragma unroll 2
        for (int c = 0; c < 32; ++c) {
            float4 v0 = __ldcs(p4 + (size_t)c * 60);
            float4 v1 = __ldcs(p4 + (size_t)c * 60 + 1);
            float hp = s_ph[g * 32 + c];
            float w  = s_sw[g * 32 + c];
            a0.x += tanh_fast(v0.x + hp) * w;
            a0.y += tanh_fast(v0.y + hp) * w;
            a0.z += tanh_fast(v0.z + hp) * w;
            a0.w += tanh_fast(v0.w + hp) * w;
            a1.x += tanh_fast(v1.x + hp) * w;
            a1.y += tanh_fast(v1.y + hp) * w;
            a1.z += tanh_fast(v1.z + hp) * w;
            a1.w += tanh_fast(v1.w + hp) * w;
        }
        *reinterpret_cast<float4*>(&s_part[g][8 * t])     = a0;
        *reinterpret_cast<float4*>(&s_part[g][8 * t + 4]) = a1;
    }
    __syncthreads();

    float eval = 0.f;
    if (tid < HWW) {
        #pragma unroll
        for (int gg = 0; gg < 16; ++gg) eval += s_part[gg][tid];
    }
    const int lane = tid & 31, wid = tid >> 5;

    float v = (tid < HWW) ? eval : -3.0e38f;
    #pragma unroll
    for (int o = 16; o; o >>= 1) v = fmaxf(v, __shfl_xor_sync(0xffffffffu, v, o));
    if (lane == 0) s_red[wid] = v;
    __syncthreads();
    float m = s_red[0];
    #pragma unroll
    for (int i = 1; i < 16; ++i) m = fmaxf(m, s_red[i]);

    float e = (tid < HWW) ? __expf(eval - m) : 0.f;
    float sv = e;
    #pragma unroll
    for (int o = 16; o; o >>= 1) sv += __shfl_xor_sync(0xffffffffu, sv, o);
    if (lane == 0) s_red2[wid] = sv;
    __syncthreads();
    float tot = 0.f;
    #pragma unroll
    for (int i = 0; i < 16; ++i) tot += s_red2[i];

    if (tid < HWW) {
        const float alpha = e / tot;
        g_alpha[(size_t)b * HWW + tid] = alpha;
        alphaT[(size_t)tid * BB + b] = alpha;
    }
    if (tid < EE) {   // embeddings -> x tail
        __nv_bfloat16 h, l;
        split_bf16(emb[(size_t)b * EE + tid], h, l);
        g_xhi[(size_t)b * KX + CC + tid] = h;
        g_xlo[(size_t)b * KX + CC + tid] = l;
    }
}

// ---------------------------------------------------------------------------
// Kernel 2: context GEMV. grid (8, B), 256 threads; warp per channel row.
// ---------------------------------------------------------------------------
__global__ __launch_bounds__(256) void ctx_kernel(const float* __restrict__ cfo)
{
    const int b  = blockIdx.y;
    const int c0 = blockIdx.x * 64;
    const int tid = threadIdx.x;
    const int lane = tid & 31, w = tid >> 5;

    __shared__ __align__(16) float s_alpha[HWW];
    if (tid < HWW) s_alpha[tid] = g_alpha[(size_t)b * HWW + tid];
    __syncthreads();

    const float4* a4 = reinterpret_cast<const float4*>(s_alpha);
    float4 aa = a4[lane];
    float4 a2 = (lane < 28) ? a4[lane + 32] : make_float4(0.f, 0.f, 0.f, 0.f);

    #pragma unroll 2
    for (int r = 0; r < 8; ++r) {
        const int c = c0 + w * 8 + r;
        const float4* rp = reinterpret_cast<const float4*>(
            cfo + ((size_t)b * CC + c) * HWW);
        float4 vv = __ldcs(rp + lane);
        float s = vv.x * aa.x + vv.y * aa.y + vv.z * aa.z + vv.w * aa.w;
        if (lane < 28) {
            float4 v2 = __ldcs(rp + lane + 32);
            s += v2.x * a2.x + v2.y * a2.y + v2.z * a2.z + v2.w * a2.w;
        }
        #pragma unroll
        for (int o = 16; o; o >>= 1) s += __shfl_xor_sync(0xffffffffu, s, o);
        if (lane == 0) {
            __nv_bfloat16 h, l;
            split_bf16(s, h, l);
            g_xhi[(size_t)b * KX + c] = h;
            g_xlo[(size_t)b * KX + c] = l;
        }
    }
}

// ---------------------------------------------------------------------------
// Kernel 3: gate GEMMs on tensor cores (bf16 split, 3-MMA), ldmatrix loads.
// ---------------------------------------------------------------------------
#define ASTR 40   // bf16 row stride: 80 bytes (16B-aligned rows, LDSM conflict-free)

__device__ __forceinline__ void mma16816(float* c, const uint32_t* a, const uint32_t* b) {
    asm volatile(
        "mma.sync.aligned.m16n8k16.row.col.f32.bf16.bf16.f32 "
        "{%0,%1,%2,%3}, {%4,%5,%6,%7}, {%8,%9}, {%0,%1,%2,%3};"
        : "+f"(c[0]), "+f"(c[1]), "+f"(c[2]), "+f"(c[3])
        : "r"(a[0]), "r"(a[1]), "r"(a[2]), "r"(a[3]),
          "r"(b[0]), "r"(b[1]));
}
__device__ __forceinline__ void ldsm4(uint32_t* r, const __nv_bfloat16* p) {
    uint32_t a = (uint32_t)__cvta_generic_to_shared(p);
    asm volatile("ldmatrix.sync.aligned.m8n8.x4.shared.b16 {%0,%1,%2,%3}, [%4];"
                 : "=r"(r[0]), "=r"(r[1]), "=r"(r[2]), "=r"(r[3]) : "r"(a));
}

__global__ __launch_bounds__(128) void gemm_gates(
    const float* __restrict__ b_ih, const float* __restrict__ b_hh)
{
    const int z = blockIdx.z;
    const __nv_bfloat16* Ahi = z ? g_hhi   : g_xhi;
    const __nv_bfloat16* Alo = z ? g_hlo   : g_xlo;
    const __nv_bfloat16* Bhi = z ? g_whhhi : g_wihhi;
    const __nv_bfloat16* Blo = z ? g_whhlo : g_wihlo;
    const float*         bias = z ? b_hh   : b_ih;
    float*               outp = z ? g_gh   : g_gi;
    const int            K    = z ? CC     : KX;

    __shared__ __align__(16) __nv_bfloat16 sAh[64 * ASTR];
    __shared__ __align__(16) __nv_bfloat16 sAl[64 * ASTR];
    __shared__ __align__(16) __nv_bfloat16 sBh[64 * ASTR];
    __shared__ __align__(16) __nv_bfloat16 sBl[64 * ASTR];

    const int tid  = threadIdx.x;
    const int lane = tid & 31;
    const int wrp  = tid >> 5;
    const int warp_m = wrp >> 1;
    const int warp_n = wrp & 1;
    const int gID = lane >> 2;
    const int tig = lane & 3;
    const int m0 = blockIdx.y * 64;
    const int n0 = blockIdx.x * 64;

    // ldmatrix lane->row/col mapping
    const int a_rowl = lane & 15;
    const int a_kh   = (lane >> 4) * 8;
    const int b_rowl = ((lane >> 4) * 8) + (lane & 7);
    const int b_kh   = ((lane >> 3) & 1) * 8;

    float acc[2][4][4];
    #pragma unroll
    for (int i = 0; i < 2; ++i)
        #pragma unroll
        for (int j = 0; j < 4; ++j)
            #pragma unroll
            for (int k = 0; k < 4; ++k) acc[i][j][k] = 0.f;

    const int T = K / 32;
    uint4 pa[2], pal[2], pb[2], pbl[2];

    #pragma unroll
    for (int j = 0; j < 2; ++j) {
        int u = tid + 128 * j;
        int row = u >> 2, seg = u & 3;
        pa [j] = *reinterpret_cast<const uint4*>(Ahi + (size_t)(m0 + row) * K + seg * 8);
        pal[j] = *reinterpret_cast<const uint4*>(Alo + (size_t)(m0 + row) * K + seg * 8);
        pb [j] = *reinterpret_cast<const uint4*>(Bhi + (size_t)(n0 + row) * K + seg * 8);
        pbl[j] = *reinterpret_cast<const uint4*>(Blo + (size_t)(n0 + row) * K + seg * 8);
    }

    for (int tIdx = 0; tIdx < T; ++tIdx) {
        __syncthreads();
        #pragma unroll
        for (int j = 0; j < 2; ++j) {
            int u = tid + 128 * j;
            int row = u >> 2, seg = u & 3;
            *reinterpret_cast<uint4*>(&sAh[row * ASTR + seg * 8]) = pa[j];
            *reinterpret_cast<uint4*>(&sAl[row * ASTR + seg * 8]) = pal[j];
            *reinterpret_cast<uint4*>(&sBh[row * ASTR + seg * 8]) = pb[j];
            *reinterpret_cast<uint4*>(&sBl[row * ASTR + seg * 8]) = pbl[j];
        }
        __syncthreads();

        if (tIdx + 1 < T) {
            const int kk = (tIdx + 1) * 32;
            #pragma unroll
            for (int j = 0; j < 2; ++j) {
                int u = tid + 128 * j;
                int row = u >> 2, seg = u & 3;
                pa [j] = *reinterpret_cast<const uint4*>(Ahi + (size_t)(m0 + row) * K + kk + seg * 8);
                pal[j] = *reinterpret_cast<const uint4*>(Alo + (size_t)(m0 + row) * K + kk + seg * 8);
                pb [j] = *reinterpret_cast<const uint4*>(Bhi + (size_t)(n0 + row) * K + kk + seg * 8);
                pbl[j] = *reinterpret_cast<const uint4*>(Blo + (size_t)(n0 + row) * K + kk + seg * 8);
            }
        }

        #pragma unroll
        for (int k8 = 0; k8 < 2; ++k8) {
            const int kb = k8 * 16;
            uint32_t ah[2][4], al[2][4];
            #pragma unroll
            for (int m2 = 0; m2 < 2; ++m2) {
                const int r = warp_m * 32 + m2 * 16 + a_rowl;
                ldsm4(ah[m2], &sAh[r * ASTR + kb + a_kh]);
                ldsm4(al[m2], &sAl[r * ASTR + kb + a_kh]);
            }
            uint32_t bh[4][2], bl[4][2];
            #pragma unroll
            for (int p = 0; p < 2; ++p) {
                const int r = warp_n * 32 + p * 16 + b_rowl;
                uint32_t t4[4];
                ldsm4(t4, &sBh[r * ASTR + kb + b_kh]);
                bh[2 * p][0] = t4[0]; bh[2 * p][1] = t4[1];
                bh[2 * p + 1][0] = t4[2]; bh[2 * p + 1][1] = t4[3];
                ldsm4(t4, &sBl[r * ASTR + kb + b_kh]);
                bl[2 * p][0] = t4[0]; bl[2 * p][1] = t4[1];
                bl[2 * p + 1][0] = t4[2]; bl[2 * p + 1][1] = t4[3];
            }
            #pragma unroll
            for (int m2 = 0; m2 < 2; ++m2)
                #pragma unroll
                for (int n4 = 0; n4 < 4; ++n4) {
                    mma16816(acc[m2][n4], ah[m2], bh[n4]);
                    mma16816(acc[m2][n4], ah[m2], bl[n4]);
                    mma16816(acc[m2][n4], al[m2], bh[n4]);
                }
        }
    }

    #pragma unroll
    for (int m2 = 0; m2 < 2; ++m2) {
        #pragma unroll
        for (int n4 = 0; n4 < 4; ++n4) {
            int r = m0 + warp_m * 32 + m2 * 16 + gID;
            int cb = n0 + warp_n * 32 + n4 * 8 + tig * 2;
            float2 bv = *reinterpret_cast<const float2*>(bias + cb);
            float2 o0, o1;
            o0.x = acc[m2][n4][0] + bv.x;
            o0.y = acc[m2][n4][1] + bv.y;
            o1.x = acc[m2][n4][2] + bv.x;
            o1.y = acc[m2][n4][3] + bv.y;
            *reinterpret_cast<float2*>(outp + (size_t)r * GATES + cb) = o0;
            *reinterpret_cast<float2*>(outp + (size_t)(r + 8) * GATES + cb) = o1;
        }
    }
}

// ---------------------------------------------------------------------------
// Kernel 4: GRU combine, float4 wide.
// ---------------------------------------------------------------------------
__global__ __launch_bounds__(256) void gru_kernel(
    const float* __restrict__ h, float* __restrict__ out)
{
    const int i4 = blockIdx.x * 256 + threadIdx.x;   // float4 index over B*C/4
    const int b = i4 >> 7;          // 512/4 = 128 float4 per row
    const int c4 = i4 & 127;
    const float4* pi = reinterpret_cast<const float4*>(g_gi + (size_t)b * GATES) + c4;
    const float4* pg = reinterpret_cast<const float4*>(g_gh + (size_t)b * GATES) + c4;
    float4 ir = pi[0],   hr = pg[0];
    float4 iz = pi[128], hz = pg[128];
    float4 in = pi[256], hn = pg[256];
    float4 hv = reinterpret_cast<const float4*>(h)[i4];
    float4 o;
    {
        float r = sigmoid_fast(ir.x + hr.x), z = sigmoid_fast(iz.x + hz.x);
        float n = tanh_fast(in.x + r * hn.x); o.x = (1.f - z) * n + z * hv.x;
    }
    {
        float r = sigmoid_fast(ir.y + hr.y), z = sigmoid_fast(iz.y + hz.y);
        float n = tanh_fast(in.y + r * hn.y); o.y = (1.f - z) * n + z * hv.y;
    }
    {
        float r = sigmoid_fast(ir.z + hr.z), z = sigmoid_fast(iz.z + hz.z);
        float n = tanh_fast(in.z + r * hn.z); o.z = (1.f - z) * n + z * hv.z;
    }
    {
        float r = sigmoid_fast(ir.w + hr.w), z = sigmoid_fast(iz.w + hz.w);
        float n = tanh_fast(in.w + r * hn.w); o.w = (1.f - z) * n + z * hv.w;
    }
    reinterpret_cast<float4*>(out)[i4] = o;
}

// ---------------------------------------------------------------------------
extern "C" void kernel_launch(void* const* d_in, const int* in_sizes, int n_in,
                              void* d_out, int out_size) {
    const float* prev_hidden       = (const float*)d_in[0];
    const float* conv_feats        = (const float*)d_in[1];
    const float* conv_feats_origin = (const float*)d_in[2];
    const float* cur_embeddings    = (const float*)d_in[3];
    const float* score_w           = (const float*)d_in[4];
    const float* w_ih              = (const float*)d_in[5];
    const float* w_hh              = (const float*)d_in[6];
    const float* b_ih              = (const float*)d_in[7];
    const float* b_hh              = (const float*)d_in[8];

    float* out        = (float*)d_out;
    float* out_hidden = out;                      // [B, C]
    float* out_alphaT = out + (size_t)BB * CC;    // [HW, B]

    split3_kernel<<<(N1 + N2 + N3) / 1024, 256>>>(w_ih, w_hh, prev_hidden);

    score_kernel<<<BB, 512>>>(prev_hidden, conv_feats, cur_embeddings,
                              score_w, out_alphaT);

    dim3 gc(CC / 64, BB);                         // (8, 512)
    ctx_kernel<<<gc, 256>>>(conv_feats_origin);

    dim3 g(GATES / 64, BB / 64, 2);               // (24, 8, 2) = 384 CTAs
    gemm_gates<<<g, 128>>>(b_ih, b_hh);

    gru_kernel<<<(BB * CC) / 1024, 256>>>(prev_hidden, out_hidden);
}

// round 4
// speedup vs baseline: 1.6515x; 1.0130x over previous
#include <cuda_runtime.h>
#include <cuda_bf16.h>
#include <cstdint>

#define BB   512
#define CC   512
#define EE   128
#define HWW  240
#define GATES 1536   // 3*C
#define KX    640    // C+E

// -------- scratch (static device arrays; no allocation allowed) -----------
__device__ float g_gi [BB * GATES];   // split 0 partial (no bias)
__device__ float g_gi2[BB * GATES];   // split 1 partial
__device__ float g_gh [BB * GATES];
__device__ float g_gh2[BB * GATES];
__device__ float g_alpha[BB * HWW];

__device__ __nv_bfloat16 g_xhi [BB * KX];
__device__ __nv_bfloat16 g_xlo [BB * KX];
__device__ __nv_bfloat16 g_hhi [BB * CC];
__device__ __nv_bfloat16 g_hlo [BB * CC];
__device__ __nv_bfloat16 g_wihhi[GATES * KX];
__device__ __nv_bfloat16 g_wihlo[GATES * KX];
__device__ __nv_bfloat16 g_whhhi[GATES * CC];
__device__ __nv_bfloat16 g_whhlo[GATES * CC];

__device__ __forceinline__ float tanh_fast(float x) {
    float y; asm("tanh.approx.f32 %0, %1;" : "=f"(y) : "f"(x)); return y;
}
__device__ __forceinline__ float sigmoid_fast(float x) {
    return 0.5f * tanh_fast(0.5f * x) + 0.5f;
}
__device__ __forceinline__ void split_bf16(float v, __nv_bfloat16& hi, __nv_bfloat16& lo) {
    hi = __float2bfloat16(v);
    lo = __float2bfloat16(v - __bfloat162float(hi));
}

// ---------------------------------------------------------------------------
// split3: fp32 -> (bf16 hi, bf16 lo) for w_ih, w_hh, prev_hidden, float4-wide.
// ---------------------------------------------------------------------------
#define N1 (GATES * KX)
#define N2 (GATES * CC)
#define N3 (BB * CC)

__global__ __launch_bounds__(256) void split3_kernel(
    const float* __restrict__ w_ih, const float* __restrict__ w_hh,
    const float* __restrict__ h)
{
    int i = blockIdx.x * 256 + threadIdx.x;
    const float* src; __nv_bfloat16 *hi, *lo; int off;
    if (i < N1 / 4)            { src = w_ih; hi = g_wihhi; lo = g_wihlo; off = i; }
    else if (i < (N1 + N2) / 4){ src = w_hh; hi = g_whhhi; lo = g_whhlo; off = i - N1 / 4; }
    else                       { src = h;    hi = g_hhi;   lo = g_hlo;   off = i - (N1 + N2) / 4; }

    float4 v = reinterpret_cast<const float4*>(src)[off];
    __nv_bfloat16 h0, l0, h1, l1, h2, l2, h3, l3;
    split_bf16(v.x, h0, l0); split_bf16(v.y, h1, l1);
    split_bf16(v.z, h2, l2); split_bf16(v.w, h3, l3);
    __nv_bfloat162 ph0 = {h0, h1}, ph1 = {h2, h3};
    __nv_bfloat162 pl0 = {l0, l1}, pl1 = {l2, l3};
    uint2 uh = {*(uint32_t*)&ph0, *(uint32_t*)&ph1};
    uint2 ul = {*(uint32_t*)&pl0, *(uint32_t*)&pl1};
    reinterpret_cast<uint2*>(hi)[off] = uh;
    reinterpret_cast<uint2*>(lo)[off] = ul;
}

// ---------------------------------------------------------------------------
// Kernel 1: score + softmax. One block per b, 512 threads.
// ---------------------------------------------------------------------------
__global__ __launch_bounds__(512) void score_kernel(
    const float* __restrict__ ph,
    const float* __restrict__ cf,
    const float* __restrict__ emb,
    const float* __restrict__ sw,
    float* __restrict__ alphaT)
{
    const int b   = blockIdx.x;
    const int tid = threadIdx.x;

    __shared__ __align__(16) float s_ph[CC];
    __shared__ __align__(16) float s_sw[CC];
    __shared__ __align__(16) float s_part[16][HWW];
    __shared__ float s_red[16];
    __shared__ float s_red2[16];

    for (int i = tid; i < CC; i += 512) {
        s_ph[i] = ph[(size_t)b * CC + i];
        s_sw[i] = sw[i];
    }
    __syncthreads();

    const int g = tid >> 5;
    const int t = tid & 31;
    if (t < 30) {
        const float4* p4 = reinterpret_cast<const float4*>(
            cf + ((size_t)b * CC + g * 32) * HWW) + 2 * t;
        float4 a0 = make_float4(0.f, 0.f, 0.f, 0.f);
        float4 a1 = make_float4(0.f, 0.f, 0.f, 0.f);
        #pragma unroll 4
        for (int c = 0; c < 32; ++c) {
            float4 v0 = __ldcs(p4 + (size_t)c * 60);
            float4 v1 = __ldcs(p4 + (size_t)c * 60 + 1);
            float hp = s_ph[g * 32 + c];
            float w  = s_sw[g * 32 + c];
            a0.x += tanh_fast(v0.x + hp) * w;
            a0.y += tanh_fast(v0.y + hp) * w;
            a0.z += tanh_fast(v0.z + hp) * w;
            a0.w += tanh_fast(v0.w + hp) * w;
            a1.x += tanh_fast(v1.x + hp) * w;
            a1.y += tanh_fast(v1.y + hp) * w;
            a1.z += tanh_fast(v1.z + hp) * w;
            a1.w += tanh_fast(v1.w + hp) * w;
        }
        *reinterpret_cast<float4*>(&s_part[g][8 * t])     = a0;
        *reinterpret_cast<float4*>(&s_part[g][8 * t + 4]) = a1;
    }
    __syncthreads();

    float eval = 0.f;
    if (tid < HWW) {
        #pragma unroll
        for (int gg = 0; gg < 16; ++gg) eval += s_part[gg][tid];
    }
    const int lane = tid & 31, wid = tid >> 5;

    float v = (tid < HWW) ? eval : -3.0e38f;
    #pragma unroll
    for (int o = 16; o; o >>= 1) v = fmaxf(v, __shfl_xor_sync(0xffffffffu, v, o));
    if (lane == 0) s_red[wid] = v;
    __syncthreads();
    float m = s_red[0];
    #pragma unroll
    for (int i = 1; i < 16; ++i) m = fmaxf(m, s_red[i]);

    float e = (tid < HWW) ? __expf(eval - m) : 0.f;
    float sv = e;
    #pragma unroll
    for (int o = 16; o; o >>= 1) sv += __shfl_xor_sync(0xffffffffu, sv, o);
    if (lane == 0) s_red2[wid] = sv;
    __syncthreads();
    float tot = 0.f;
    #pragma unroll
    for (int i = 0; i < 16; ++i) tot += s_red2[i];

    if (tid < HWW) {
        const float alpha = e / tot;
        g_alpha[(size_t)b * HWW + tid] = alpha;
        alphaT[(size_t)tid * BB + b] = alpha;
    }
    if (tid < EE) {
        __nv_bfloat16 h, l;
        split_bf16(emb[(size_t)b * EE + tid], h, l);
        g_xhi[(size_t)b * KX + CC + tid] = h;
        g_xlo[(size_t)b * KX + CC + tid] = l;
    }
}

// ---------------------------------------------------------------------------
// Kernel 2: context GEMV. grid (8, B), 256 threads; warp per channel row.
// ---------------------------------------------------------------------------
__global__ __launch_bounds__(256) void ctx_kernel(const float* __restrict__ cfo)
{
    const int b  = blockIdx.y;
    const int c0 = blockIdx.x * 64;
    const int tid = threadIdx.x;
    const int lane = tid & 31, w = tid >> 5;

    __shared__ __align__(16) float s_alpha[HWW];
    if (tid < HWW) s_alpha[tid] = g_alpha[(size_t)b * HWW + tid];
    __syncthreads();

    const float4* a4 = reinterpret_cast<const float4*>(s_alpha);
    float4 aa = a4[lane];
    float4 a2 = (lane < 28) ? a4[lane + 32] : make_float4(0.f, 0.f, 0.f, 0.f);

    #pragma unroll 2
    for (int r = 0; r < 8; ++r) {
        const int c = c0 + w * 8 + r;
        const float4* rp = reinterpret_cast<const float4*>(
            cfo + ((size_t)b * CC + c) * HWW);
        float4 vv = __ldcs(rp + lane);
        float s = vv.x * aa.x + vv.y * aa.y + vv.z * aa.z + vv.w * aa.w;
        if (lane < 28) {
            float4 v2 = __ldcs(rp + lane + 32);
            s += v2.x * a2.x + v2.y * a2.y + v2.z * a2.z + v2.w * a2.w;
        }
        #pragma unroll
        for (int o = 16; o; o >>= 1) s += __shfl_xor_sync(0xffffffffu, s, o);
        if (lane == 0) {
            __nv_bfloat16 h, l;
            split_bf16(s, h, l);
            g_xhi[(size_t)b * KX + c] = h;
            g_xlo[(size_t)b * KX + c] = l;
        }
    }
}

// ---------------------------------------------------------------------------
// Kernel 3: gate GEMMs, bf16 3-MMA, split-K=2, cp.async double buffer.
// grid (24, 8, 4): z&1 = which gemm, z>>1 = k-split. No bias here.
// ---------------------------------------------------------------------------
#define ASTR 40   // bf16 row stride: 80 bytes

__device__ __forceinline__ void mma16816(float* c, const uint32_t* a, const uint32_t* b) {
    asm volatile(
        "mma.sync.aligned.m16n8k16.row.col.f32.bf16.bf16.f32 "
        "{%0,%1,%2,%3}, {%4,%5,%6,%7}, {%8,%9}, {%0,%1,%2,%3};"
        : "+f"(c[0]), "+f"(c[1]), "+f"(c[2]), "+f"(c[3])
        : "r"(a[0]), "r"(a[1]), "r"(a[2]), "r"(a[3]),
          "r"(b[0]), "r"(b[1]));
}
__device__ __forceinline__ void ldsm4(uint32_t* r, const __nv_bfloat16* p) {
    uint32_t a = (uint32_t)__cvta_generic_to_shared(p);
    asm volatile("ldmatrix.sync.aligned.m8n8.x4.shared.b16 {%0,%1,%2,%3}, [%4];"
                 : "=r"(r[0]), "=r"(r[1]), "=r"(r[2]), "=r"(r[3]) : "r"(a));
}
__device__ __forceinline__ void cpasync16(uint32_t dst, const void* src) {
    asm volatile("cp.async.cg.shared.global [%0], [%1], 16;" :: "r"(dst), "l"(src));
}

__global__ __launch_bounds__(128) void gemm_gates()
{
    const int z      = blockIdx.z;
    const int gemmi  = z & 1;       // 0: gi (K=640), 1: gh (K=512)
    const int split  = z >> 1;      // 0 or 1

    const __nv_bfloat16* Ahi = gemmi ? g_hhi   : g_xhi;
    const __nv_bfloat16* Alo = gemmi ? g_hlo   : g_xlo;
    const __nv_bfloat16* Bhi = gemmi ? g_whhhi : g_wihhi;
    const __nv_bfloat16* Blo = gemmi ? g_whhlo : g_wihlo;
    float* outp = gemmi ? (split ? g_gh2 : g_gh) : (split ? g_gi2 : g_gi);
    const int K     = gemmi ? CC : KX;
    const int Khalf = K >> 1;
    const int koff  = split * Khalf;
    const int T     = Khalf / 32;   // 8 or 10

    __shared__ __align__(16) __nv_bfloat16 sAh[2][64 * ASTR];
    __shared__ __align__(16) __nv_bfloat16 sAl[2][64 * ASTR];
    __shared__ __align__(16) __nv_bfloat16 sBh[2][64 * ASTR];
    __shared__ __align__(16) __nv_bfloat16 sBl[2][64 * ASTR];

    const int tid  = threadIdx.x;
    const int lane = tid & 31;
    const int wrp  = tid >> 5;
    const int warp_m = wrp >> 1;
    const int warp_n = wrp & 1;
    const int gID = lane >> 2;
    const int tig = lane & 3;
    const int m0 = blockIdx.y * 64;
    const int n0 = blockIdx.x * 64;

    const int a_rowl = lane & 15;
    const int a_kh   = (lane >> 4) * 8;
    const int b_rowl = ((lane >> 4) * 8) + (lane & 7);
    const int b_kh   = ((lane >> 3) & 1) * 8;

    // per-thread load coordinates (two 16B chunks per array per stage)
    const int lrow0 = tid >> 2,         lseg0 = (tid & 3) * 8;
    const int lrow1 = (tid + 128) >> 2, lseg1 = (tid & 3) * 8;

    float acc[2][4][4];
    #pragma unroll
    for (int i = 0; i < 2; ++i)
        #pragma unroll
        for (int j = 0; j < 4; ++j)
            #pragma unroll
            for (int k = 0; k < 4; ++k) acc[i][j][k] = 0.f;

    auto load_stage = [&](int s, int kt) {
        const size_t kbase = (size_t)koff + kt * 32;
        {
            size_t ga = (size_t)(m0 + lrow0) * K + kbase + lseg0;
            size_t gb = (size_t)(n0 + lrow0) * K + kbase + lseg0;
            int so = lrow0 * ASTR + lseg0;
            cpasync16((uint32_t)__cvta_generic_to_shared(&sAh[s][so]), Ahi + ga);
            cpasync16((uint32_t)__cvta_generic_to_shared(&sAl[s][so]), Alo + ga);
            cpasync16((uint32_t)__cvta_generic_to_shared(&sBh[s][so]), Bhi + gb);
            cpasync16((uint32_t)__cvta_generic_to_shared(&sBl[s][so]), Blo + gb);
        }
        {
            size_t ga = (size_t)(m0 + lrow1) * K + kbase + lseg1;
            size_t gb = (size_t)(n0 + lrow1) * K + kbase + lseg1;
            int so = lrow1 * ASTR + lseg1;
            cpasync16((uint32_t)__cvta_generic_to_shared(&sAh[s][so]), Ahi + ga);
            cpasync16((uint32_t)__cvta_generic_to_shared(&sAl[s][so]), Alo + ga);
            cpasync16((uint32_t)__cvta_generic_to_shared(&sBh[s][so]), Bhi + gb);
            cpasync16((uint32_t)__cvta_generic_to_shared(&sBl[s][so]), Blo + gb);
        }
        asm volatile("cp.async.commit_group;");
    };

    load_stage(0, 0);
    load_stage(1, 1);

    for (int t = 0; t < T; ++t) {
        if (t + 1 < T) { asm volatile("cp.async.wait_group 1;"); }
        else           { asm volatile("cp.async.wait_group 0;"); }
        __syncthreads();

        const int st = t & 1;
        #pragma unroll
        for (int k8 = 0; k8 < 2; ++k8) {
            const int kb = k8 * 16;
            uint32_t ah[2][4], al[2][4];
            #pragma unroll
            for (int m2 = 0; m2 < 2; ++m2) {
                const int r = warp_m * 32 + m2 * 16 + a_rowl;
                ldsm4(ah[m2], &sAh[st][r * ASTR + kb + a_kh]);
                ldsm4(al[m2], &sAl[st][r * ASTR + kb + a_kh]);
            }
            uint32_t bh[4][2], bl[4][2];
            #pragma unroll
            for (int p = 0; p < 2; ++p) {
                const int r = warp_n * 32 + p * 16 + b_rowl;
                uint32_t t4[4];
                ldsm4(t4, &sBh[st][r * ASTR + kb + b_kh]);
                bh[2 * p][0] = t4[0]; bh[2 * p][1] = t4[1];
                bh[2 * p + 1][0] = t4[2]; bh[2 * p + 1][1] = t4[3];
                ldsm4(t4, &sBl[st][r * ASTR + kb + b_kh]);
                bl[2 * p][0] = t4[0]; bl[2 * p][1] = t4[1];
                bl[2 * p + 1][0] = t4[2]; bl[2 * p + 1][1] = t4[3];
            }
            #pragma unroll
            for (int m2 = 0; m2 < 2; ++m2)
                #pragma unroll
                for (int n4 = 0; n4 < 4; ++n4) {
                    mma16816(acc[m2][n4], ah[m2], bh[n4]);
                    mma16816(acc[m2][n4], ah[m2], bl[n4]);
                    mma16816(acc[m2][n4], al[m2], bh[n4]);
                }
        }
        __syncthreads();
        if (t + 2 < T) load_stage(st, t + 2);
    }

    #pragma unroll
    for (int m2 = 0; m2 < 2; ++m2) {
        #pragma unroll
        for (int n4 = 0; n4 < 4; ++n4) {
            int r = m0 + warp_m * 32 + m2 * 16 + gID;
            int cb = n0 + warp_n * 32 + n4 * 8 + tig * 2;
            float2 o0 = {acc[m2][n4][0], acc[m2][n4][1]};
            float2 o1 = {acc[m2][n4][2], acc[m2][n4][3]};
            *reinterpret_cast<float2*>(outp + (size_t)r * GATES + cb) = o0;
            *reinterpret_cast<float2*>(outp + (size_t)(r + 8) * GATES + cb) = o1;
        }
    }
}

// ---------------------------------------------------------------------------
// Kernel 4: GRU combine; sums split-K partials and biases.
// ---------------------------------------------------------------------------
__global__ __launch_bounds__(256) void gru_kernel(
    const float* __restrict__ h, const float* __restrict__ b_ih,
    const float* __restrict__ b_hh, float* __restrict__ out)
{
    const int i4 = blockIdx.x * 256 + threadIdx.x;
    const int b = i4 >> 7;
    const int c4 = i4 & 127;
    const float4* pi  = reinterpret_cast<const float4*>(g_gi  + (size_t)b * GATES) + c4;
    const float4* pi2 = reinterpret_cast<const float4*>(g_gi2 + (size_t)b * GATES) + c4;
    const float4* pg  = reinterpret_cast<const float4*>(g_gh  + (size_t)b * GATES) + c4;
    const float4* pg2 = reinterpret_cast<const float4*>(g_gh2 + (size_t)b * GATES) + c4;
    const float4* bi  = reinterpret_cast<const float4*>(b_ih) + c4;
    const float4* bh  = reinterpret_cast<const float4*>(b_hh) + c4;

    float4 hv = reinterpret_cast<const float4*>(h)[i4];
    float4 o;
    #pragma unroll
    for (int gsel = 0; gsel < 1; ++gsel) {} // keep structure simple

    float4 ir0 = pi[0],   ir1 = pi2[0],   hr0 = pg[0],   hr1 = pg2[0];
    float4 iz0 = pi[128], iz1 = pi2[128], hz0 = pg[128], hz1 = pg2[128];
    float4 in0 = pi[256], in1 = pi2[256], hn0 = pg[256], hn1 = pg2[256];
    float4 bir = bi[0],   biz = bi[128],  bin = bi[256];
    float4 bhr = bh[0],   bhz = bh[128],  bhn = bh[256];

    {
        float gi_r = ir0.x + ir1.x + bir.x, gh_r = hr0.x + hr1.x + bhr.x;
        float gi_z = iz0.x + iz1.x + biz.x, gh_z = hz0.x + hz1.x + bhz.x;
        float gi_n = in0.x + in1.x + bin.x, gh_n = hn0.x + hn1.x + bhn.x;
        float r = sigmoid_fast(gi_r + gh_r), zz = sigmoid_fast(gi_z + gh_z);
        float n = tanh_fast(gi_n + r * gh_n);
        o.x = (1.f - zz) * n + zz * hv.x;
    }
    {
        float gi_r = ir0.y + ir1.y + bir.y, gh_r = hr0.y + hr1.y + bhr.y;
        float gi_z = iz0.y + iz1.y + biz.y, gh_z = hz0.y + hz1.y + bhz.y;
        float gi_n = in0.y + in1.y + bin.y, gh_n = hn0.y + hn1.y + bhn.y;
        float r = sigmoid_fast(gi_r + gh_r), zz = sigmoid_fast(gi_z + gh_z);
        float n = tanh_fast(gi_n + r * gh_n);
        o.y = (1.f - zz) * n + zz * hv.y;
    }
    {
        float gi_r = ir0.z + ir1.z + bir.z, gh_r = hr0.z + hr1.z + bhr.z;
        float gi_z = iz0.z + iz1.z + biz.z, gh_z = hz0.z + hz1.z + bhz.z;
        float gi_n = in0.z + in1.z + bin.z, gh_n = hn0.z + hn1.z + bhn.z;
        float r = sigmoid_fast(gi_r + gh_r), zz = sigmoid_fast(gi_z + gh_z);
        float n = tanh_fast(gi_n + r * gh_n);
        o.z = (1.f - zz) * n + zz * hv.z;
    }
    {
        float gi_r = ir0.w + ir1.w + bir.w, gh_r = hr0.w + hr1.w + bhr.w;
        float gi_z = iz0.w + iz1.w + biz.w, gh_z = hz0.w + hz1.w + bhz.w;
        float gi_n = in0.w + in1.w + bin.w, gh_n = hn0.w + hn1.w + bhn.w;
        float r = sigmoid_fast(gi_r + gh_r), zz = sigmoid_fast(gi_z + gh_z);
        float n = tanh_fast(gi_n + r * gh_n);
        o.w = (1.f - zz) * n + zz * hv.w;
    }
    reinterpret_cast<float4*>(out)[i4] = o;
}

// ---------------------------------------------------------------------------
extern "C" void kernel_launch(void* const* d_in, const int* in_sizes, int n_in,
                              void* d_out, int out_size) {
    const float* prev_hidden       = (const float*)d_in[0];
    const float* conv_feats        = (const float*)d_in[1];
    const float* conv_feats_origin = (const float*)d_in[2];
    const float* cur_embeddings    = (const float*)d_in[3];
    const float* score_w           = (const float*)d_in[4];
    const float* w_ih              = (const float*)d_in[5];
    const float* w_hh              = (const float*)d_in[6];
    const float* b_ih              = (const float*)d_in[7];
    const float* b_hh              = (const float*)d_in[8];

    float* out        = (float*)d_out;
    float* out_hidden = out;                      // [B, C]
    float* out_alphaT = out + (size_t)BB * CC;    // [HW, B]

    split3_kernel<<<(N1 + N2 + N3) / 1024, 256>>>(w_ih, w_hh, prev_hidden);

    score_kernel<<<BB, 512>>>(prev_hidden, conv_feats, cur_embeddings,
                              score_w, out_alphaT);

    dim3 gc(CC / 64, BB);                         // (8, 512)
    ctx_kernel<<<gc, 256>>>(conv_feats_origin);

    dim3 g(GATES / 64, BB / 64, 4);               // (24, 8, 4) = 768 CTAs
    gemm_gates<<<g, 128>>>();

    gru_kernel<<<(BB * CC) / 1024, 256>>>(prev_hidden, b_ih, b_hh, out_hidden);
}